// round 4
// baseline (speedup 1.0000x reference)
#include <cuda_runtime.h>
#include <cstdint>
#include <cstddef>

#define T_TOK 2048
#define LM    4096
#define VIS   32768
#define FF    1024
#define NB    16

// ---------------- scratch (device globals; no allocations allowed) ----------
__device__ float g_yv_part[64][NB][FF];   // split-K partials for vision GEMM
__device__ float g_yv[NB][FF];            // vision projection per batch [16,1024]
__device__ float g_h0[T_TOK][FF];         // ping
__device__ float g_h1[T_TOK][FF];         // pong
__device__ int   g_tbi[T_TOK];            // normalized int32 token_batch_idx

__device__ __forceinline__ uint32_t to_tf32(float x) {
    uint32_t y;
    asm("cvt.rna.tf32.f32 %0, %1;" : "=r"(y) : "f"(x));
    return y;
}
__device__ __forceinline__ uint32_t smem_u32(const void* p) {
    uint32_t a;
    asm("{ .reg .u64 t; cvta.to.shared.u64 t, %1; cvt.u32.u64 %0, t; }"
        : "=r"(a) : "l"(p));
    return a;
}

// ---------------- idx dtype resolve (int64 vs int32, decided on-device) -----
__global__ void resolve_idx_kernel(const int* __restrict__ raw) {
    __shared__ int red[32];
    __shared__ int is64;
    int tid = threadIdx.x;
    int local = raw[2 * tid + 1];
    #pragma unroll
    for (int o = 16; o; o >>= 1) local += __shfl_down_sync(~0u, local, o);
    if ((tid & 31) == 0) red[tid >> 5] = local;
    __syncthreads();
    if (tid == 0) {
        int s = 0;
        for (int w = 0; w < 32; w++) s += red[w];
        is64 = (s == 0);
    }
    __syncthreads();
    int f = is64;
    for (int i = tid; i < T_TOK; i += 1024)
        g_tbi[i] = f ? raw[2 * i] : raw[i];
}

// ---------------- vision GEMM: yv[16,1024] = vis_flat[16,32768] @ W1_vis ----
__global__ void __launch_bounds__(256) vis_gemm_partial(
    const float* __restrict__ vis, const float* __restrict__ W1) {
    const int n  = blockIdx.x * 256 + threadIdx.x;
    const int kc = blockIdx.y;
    const int k0 = kc * 512;
    __shared__ float4 vs4[NB][32];
    float acc[NB];
    #pragma unroll
    for (int b = 0; b < NB; b++) acc[b] = 0.f;

    for (int ks = 0; ks < 512; ks += 128) {
        __syncthreads();
        for (int i = threadIdx.x; i < NB * 32; i += 256) {
            int b = i >> 5, q = i & 31;
            vs4[b][q] = *(const float4*)&vis[(size_t)b * VIS + k0 + ks + q * 4];
        }
        __syncthreads();
        const float* Wp = &W1[(size_t)(k0 + ks) * FF + n];
        #pragma unroll 4
        for (int kk = 0; kk < 128; kk += 4) {
            float w0 = Wp[(size_t)(kk + 0) * FF];
            float w1 = Wp[(size_t)(kk + 1) * FF];
            float w2 = Wp[(size_t)(kk + 2) * FF];
            float w3 = Wp[(size_t)(kk + 3) * FF];
            #pragma unroll
            for (int b = 0; b < NB; b++) {
                float4 v = vs4[b][kk >> 2];
                acc[b] = fmaf(v.x, w0, acc[b]);
                acc[b] = fmaf(v.y, w1, acc[b]);
                acc[b] = fmaf(v.z, w2, acc[b]);
                acc[b] = fmaf(v.w, w3, acc[b]);
            }
        }
    }
    #pragma unroll
    for (int b = 0; b < NB; b++) g_yv_part[kc][b][n] = acc[b];
}

__global__ void vis_reduce() {
    int i = blockIdx.x * blockDim.x + threadIdx.x;
    int b = i >> 10, n = i & 1023;
    float s = 0.f;
    #pragma unroll 8
    for (int c = 0; c < 64; c++) s += g_yv_part[c][b][n];
    g_yv[b][n] = s;
}

// ---------------- main GEMM: C = relu(A[2048,K] @ Bw[K,1024] + bias (+ yv))
// tf32 mma.sync m16n8k8, 128x128 CTA tile, 8 warps (2m x 4n), 64x32 warp tile,
// K-tile 16, double-buffered smem, A fragments via ldmatrix.x4 (conflict-free
// stride-20 rows), B fragments via conflict-free stride-136 scalar LDS.
__global__ void __launch_bounds__(256) mlp_gemm(
    const float* __restrict__ A, const float* __restrict__ Bw,
    const float* __restrict__ bias, float* __restrict__ C,
    int K, int add_vis) {
    __shared__ __align__(16) float As[2][128][20];  // 16 cols + 4 pad (80B rows)
    __shared__ __align__(16) float Bs[2][16][136];  // 128 cols + 8 pad

    const int tid  = threadIdx.x;
    const int m0   = blockIdx.y * 128, n0 = blockIdx.x * 128;
    const int warp = tid >> 5, lane = tid & 31;
    const int wm   = warp >> 2, wn = warp & 3;
    const int g    = lane >> 2, tq = lane & 3;

    float acc[4][4][4];
    #pragma unroll
    for (int mi = 0; mi < 4; mi++)
        #pragma unroll
        for (int ni = 0; ni < 4; ni++)
            #pragma unroll
            for (int q = 0; q < 4; q++) acc[mi][ni][q] = 0.f;

    // global-load thread mapping
    const int a_row = tid >> 1;                 // 0..127
    const int a_q0  = (tid & 1) * 4;            // col 0 or 4 (second +8)
    const int b_row = tid >> 5;                 // k row 0..7 (second +8)
    const int b_q   = (tid & 31) * 4;           // n col

    // ldmatrix per-thread address offset inside an A tile
    const uint32_t as_base = smem_u32(As);
    const uint32_t a_frag_off =
        (uint32_t)(((lane & 15) * 20 + (lane >> 4) * 4) * 4);

    float4 ar0, ar1, br0, br1;
    auto gload = [&](int k0) {
        ar0 = *(const float4*)&A[(size_t)(m0 + a_row) * K + k0 + a_q0];
        ar1 = *(const float4*)&A[(size_t)(m0 + a_row) * K + k0 + a_q0 + 8];
        br0 = *(const float4*)&Bw[(size_t)(k0 + b_row) * FF + n0 + b_q];
        br1 = *(const float4*)&Bw[(size_t)(k0 + b_row + 8) * FF + n0 + b_q];
    };
    auto sstore = [&](int buf) {
        float4 t0, t1;
        t0.x = __uint_as_float(to_tf32(ar0.x));
        t0.y = __uint_as_float(to_tf32(ar0.y));
        t0.z = __uint_as_float(to_tf32(ar0.z));
        t0.w = __uint_as_float(to_tf32(ar0.w));
        t1.x = __uint_as_float(to_tf32(ar1.x));
        t1.y = __uint_as_float(to_tf32(ar1.y));
        t1.z = __uint_as_float(to_tf32(ar1.z));
        t1.w = __uint_as_float(to_tf32(ar1.w));
        *(float4*)&As[buf][a_row][a_q0]     = t0;
        *(float4*)&As[buf][a_row][a_q0 + 8] = t1;
        float4 u0, u1;
        u0.x = __uint_as_float(to_tf32(br0.x));
        u0.y = __uint_as_float(to_tf32(br0.y));
        u0.z = __uint_as_float(to_tf32(br0.z));
        u0.w = __uint_as_float(to_tf32(br0.w));
        u1.x = __uint_as_float(to_tf32(br1.x));
        u1.y = __uint_as_float(to_tf32(br1.y));
        u1.z = __uint_as_float(to_tf32(br1.z));
        u1.w = __uint_as_float(to_tf32(br1.w));
        *(float4*)&Bs[buf][b_row][b_q]     = u0;
        *(float4*)&Bs[buf][b_row + 8][b_q] = u1;
    };

    gload(0);
    sstore(0);
    __syncthreads();

    const int KT = K >> 4;
    for (int kt = 0; kt < KT; kt++) {
        const int cur = kt & 1;
        if (kt + 1 < KT) gload((kt + 1) << 4);

        const uint32_t as_cur = as_base + (uint32_t)cur * sizeof(As[0]);
        #pragma unroll
        for (int kk = 0; kk < 16; kk += 8) {
            uint32_t af[4][4];
            #pragma unroll
            for (int mi = 0; mi < 4; mi++) {
                uint32_t addr = as_cur +
                    (uint32_t)((wm * 64 + mi * 16) * 80 + kk * 4) + a_frag_off;
                asm volatile(
                    "ldmatrix.sync.aligned.m8n8.x4.shared.b16 {%0,%1,%2,%3}, [%4];"
                    : "=r"(af[mi][0]), "=r"(af[mi][1]),
                      "=r"(af[mi][2]), "=r"(af[mi][3])
                    : "r"(addr));
            }
            uint32_t bf[4][2];
            #pragma unroll
            for (int ni = 0; ni < 4; ni++) {
                int c = wn * 32 + ni * 8 + g;
                bf[ni][0] = __float_as_uint(Bs[cur][kk + tq][c]);
                bf[ni][1] = __float_as_uint(Bs[cur][kk + tq + 4][c]);
            }
            #pragma unroll
            for (int mi = 0; mi < 4; mi++)
                #pragma unroll
                for (int ni = 0; ni < 4; ni++)
                    asm volatile(
                        "mma.sync.aligned.m16n8k8.row.col.f32.tf32.tf32.f32 "
                        "{%0,%1,%2,%3}, {%4,%5,%6,%7}, {%8,%9}, {%0,%1,%2,%3};"
                        : "+f"(acc[mi][ni][0]), "+f"(acc[mi][ni][1]),
                          "+f"(acc[mi][ni][2]), "+f"(acc[mi][ni][3])
                        : "r"(af[mi][0]), "r"(af[mi][1]), "r"(af[mi][2]),
                          "r"(af[mi][3]), "r"(bf[ni][0]), "r"(bf[ni][1]));
        }

        if (kt + 1 < KT) sstore(cur ^ 1);
        __syncthreads();
    }

    // epilogue: + bias (+ yv[tbi[row]]), relu, store
    #pragma unroll
    for (int mi = 0; mi < 4; mi++) {
        int r0 = m0 + wm * 64 + mi * 16 + g;
        #pragma unroll
        for (int rr = 0; rr < 2; rr++) {
            int row = r0 + rr * 8;
            const float* yrow = nullptr;
            if (add_vis) yrow = &g_yv[g_tbi[row]][0];
            #pragma unroll
            for (int ni = 0; ni < 4; ni++) {
                int col = n0 + wn * 32 + ni * 8 + tq * 2;
                float v0 = acc[mi][ni][rr * 2 + 0] + bias[col];
                float v1 = acc[mi][ni][rr * 2 + 1] + bias[col + 1];
                if (add_vis) { v0 += yrow[col]; v1 += yrow[col + 1]; }
                v0 = fmaxf(v0, 0.f);
                v1 = fmaxf(v1, 0.f);
                C[(size_t)row * FF + col]     = v0;
                C[(size_t)row * FF + col + 1] = v1;
            }
        }
    }
}

// ---------------- head: out[2048,6] = h4 @ W5 + b5 (warp per token) ---------
__global__ void __launch_bounds__(256) head_kernel(
    const float* __restrict__ H, const float* __restrict__ W5,
    const float* __restrict__ b5, float* __restrict__ out) {
    int t    = blockIdx.x * 8 + (threadIdx.x >> 5);
    int lane = threadIdx.x & 31;
    float a0 = 0, a1 = 0, a2 = 0, a3 = 0, a4 = 0, a5 = 0;
    const float* h = H + (size_t)t * FF;
    for (int k = lane; k < FF; k += 32) {
        float hv = h[k];
        const float2 w01 = *(const float2*)&W5[(size_t)k * 6 + 0];
        const float2 w23 = *(const float2*)&W5[(size_t)k * 6 + 2];
        const float2 w45 = *(const float2*)&W5[(size_t)k * 6 + 4];
        a0 = fmaf(hv, w01.x, a0);
        a1 = fmaf(hv, w01.y, a1);
        a2 = fmaf(hv, w23.x, a2);
        a3 = fmaf(hv, w23.y, a3);
        a4 = fmaf(hv, w45.x, a4);
        a5 = fmaf(hv, w45.y, a5);
    }
    #pragma unroll
    for (int o = 16; o; o >>= 1) {
        a0 += __shfl_down_sync(~0u, a0, o);
        a1 += __shfl_down_sync(~0u, a1, o);
        a2 += __shfl_down_sync(~0u, a2, o);
        a3 += __shfl_down_sync(~0u, a3, o);
        a4 += __shfl_down_sync(~0u, a4, o);
        a5 += __shfl_down_sync(~0u, a5, o);
    }
    if (lane == 0) {
        float* o = out + (size_t)t * 6;
        o[0] = a0 + b5[0];
        o[1] = a1 + b5[1];
        o[2] = a2 + b5[2];
        o[3] = a3 + b5[3];
        o[4] = a4 + b5[4];
        o[5] = a5 + b5[5];
    }
}

// ---------------- launch -----------------------------------------------------
extern "C" void kernel_launch(void* const* d_in, const int* in_sizes, int n_in,
                              void* d_out, int out_size) {
    const float* grd     = (const float*)d_in[0];
    const float* vis     = (const float*)d_in[1];
    const int*   tbi_raw = (const int*)d_in[2];
    const float* W1 = (const float*)d_in[3];
    const float* b1 = (const float*)d_in[4];
    const float* W2 = (const float*)d_in[5];
    const float* b2 = (const float*)d_in[6];
    const float* W3 = (const float*)d_in[7];
    const float* b3 = (const float*)d_in[8];
    const float* W4 = (const float*)d_in[9];
    const float* b4 = (const float*)d_in[10];
    const float* W5 = (const float*)d_in[11];
    const float* b5 = (const float*)d_in[12];
    float* out = (float*)d_out;

    float *h0, *h1;
    cudaGetSymbolAddress((void**)&h0, g_h0);
    cudaGetSymbolAddress((void**)&h1, g_h1);

    resolve_idx_kernel<<<1, 1024>>>(tbi_raw);
    vis_gemm_partial<<<dim3(4, 64), 256>>>(vis, W1);
    vis_reduce<<<64, 256>>>();
    // layer 1: language part of W1 + gathered vision projection + b1, relu
    mlp_gemm<<<dim3(8, 16), 256>>>(grd, W1 + (size_t)VIS * FF, b1, h0, LM, 1);
    mlp_gemm<<<dim3(8, 16), 256>>>(h0, W2, b2, h1, FF, 0);
    mlp_gemm<<<dim3(8, 16), 256>>>(h1, W3, b3, h0, FF, 0);
    mlp_gemm<<<dim3(8, 16), 256>>>(h0, W4, b4, h1, FF, 0);
    head_kernel<<<256, 256>>>(h1, W5, b5, out);
}

// round 5
// speedup vs baseline: 1.2302x; 1.2302x over previous
#include <cuda_runtime.h>
#include <cstdint>
#include <cstddef>

#define T_TOK 2048
#define LM    4096
#define VIS   32768
#define FF    1024
#define NB    16
#define VKC   128                 // vision: K elements per chunk
#define NVCH  (VIS / VKC)         // 256 chunks

// ---------------- scratch (device globals; no allocations allowed) ----------
__device__ float g_yv_part[NVCH][NB][FF];   // 16 MB vision split-K partials
__device__ float g_yv[NB][FF];              // vision projection [16,1024]
__device__ float g_part[2][T_TOK][FF];      // 16 MB GEMM split-K partials
__device__ float g_h0[T_TOK][FF];           // ping
__device__ float g_h1[T_TOK][FF];           // pong
__device__ int   g_tbi[T_TOK];              // normalized token_batch_idx

__device__ __forceinline__ uint32_t to_tf32(float x) {
    uint32_t y;
    asm("cvt.rna.tf32.f32 %0, %1;" : "=r"(y) : "f"(x));
    return y;
}
__device__ __forceinline__ uint32_t smem_u32(const void* p) {
    uint32_t a;
    asm("{ .reg .u64 t; cvta.to.shared.u64 t, %1; cvt.u32.u64 %0, t; }"
        : "=r"(a) : "l"(p));
    return a;
}

// ---------------- idx dtype resolve (int64 vs int32, decided on-device) -----
__global__ void resolve_idx_kernel(const int* __restrict__ raw) {
    __shared__ int red[32];
    __shared__ int is64;
    int tid = threadIdx.x;
    int local = raw[2 * tid + 1];
    #pragma unroll
    for (int o = 16; o; o >>= 1) local += __shfl_down_sync(~0u, local, o);
    if ((tid & 31) == 0) red[tid >> 5] = local;
    __syncthreads();
    if (tid == 0) {
        int s = 0;
        for (int w = 0; w < 32; w++) s += red[w];
        is64 = (s == 0);
    }
    __syncthreads();
    int f = is64;
    for (int i = tid; i < T_TOK; i += 1024)
        g_tbi[i] = f ? raw[2 * i] : raw[i];
}

// ---------------- vision GEMM: yv[16,1024] = vis_flat[16,32768] @ W1_vis ----
// 256 chunk-blocks of 128 k; each thread owns one float4 of N (coalesced W
// float4 streaming, 2-deep MLP), vis chunk broadcast from smem.
__global__ void __launch_bounds__(256) vis_gemm_partial(
    const float* __restrict__ vis, const float* __restrict__ W1) {
    const int kc = blockIdx.x;             // 0..255
    const int k0 = kc * VKC;
    const int tid = threadIdx.x;
    __shared__ float vs[NB][VKC];          // 8 KB
    for (int i = tid; i < NB * (VKC / 4); i += 256) {
        int b = i / (VKC / 4), q = i % (VKC / 4);
        *(float4*)&vs[b][q * 4] =
            *(const float4*)&vis[(size_t)b * VIS + k0 + q * 4];
    }
    __syncthreads();

    float4 acc[NB];
    #pragma unroll
    for (int b = 0; b < NB; b++) acc[b] = make_float4(0.f, 0.f, 0.f, 0.f);

    const float* Wp = W1 + (size_t)k0 * FF + tid * 4;
    #pragma unroll 2
    for (int k = 0; k < VKC; k += 2) {
        float4 w0 = *(const float4*)(Wp + (size_t)k * FF);
        float4 w1 = *(const float4*)(Wp + (size_t)(k + 1) * FF);
        #pragma unroll
        for (int b = 0; b < NB; b++) {
            float v0 = vs[b][k], v1 = vs[b][k + 1];
            acc[b].x = fmaf(v0, w0.x, acc[b].x);
            acc[b].y = fmaf(v0, w0.y, acc[b].y);
            acc[b].z = fmaf(v0, w0.z, acc[b].z);
            acc[b].w = fmaf(v0, w0.w, acc[b].w);
            acc[b].x = fmaf(v1, w1.x, acc[b].x);
            acc[b].y = fmaf(v1, w1.y, acc[b].y);
            acc[b].z = fmaf(v1, w1.z, acc[b].z);
            acc[b].w = fmaf(v1, w1.w, acc[b].w);
        }
    }
    #pragma unroll
    for (int b = 0; b < NB; b++)
        *(float4*)&g_yv_part[kc][b][tid * 4] = acc[b];
}

__global__ void __launch_bounds__(256) vis_reduce() {
    int i = blockIdx.x * 256 + threadIdx.x;    // 16384 threads
    int b = i >> 10, n = i & 1023;
    float s = 0.f;
    #pragma unroll 8
    for (int c = 0; c < NVCH; c++) s += g_yv_part[c][b][n];
    g_yv[b][n] = s;
}

// ---------------- main GEMM (split-K=2): part[z] = A[:,z*K/2:(z+1)*K/2] @ Bw
// tf32 mma.sync m16n8k8, 128x128 CTA tile, 8 warps (2m x 4n), K-tile 16,
// double-buffered smem, A fragments via ldmatrix.x4, 2 CTAs/SM.
__global__ void __launch_bounds__(256, 2) mlp_gemm(
    const float* __restrict__ A, const float* __restrict__ Bw,
    float* __restrict__ part, int Kfull) {
    __shared__ __align__(16) float As[2][128][20];
    __shared__ __align__(16) float Bs[2][16][136];

    const int tid  = threadIdx.x;
    const int m0   = blockIdx.y * 128, n0 = blockIdx.x * 128;
    const int z    = blockIdx.z;
    const int Keff = Kfull >> 1;
    const int koff = z * Keff;
    const int warp = tid >> 5, lane = tid & 31;
    const int wm   = warp >> 2, wn = warp & 3;
    const int g    = lane >> 2, tq = lane & 3;

    float acc[4][4][4];
    #pragma unroll
    for (int mi = 0; mi < 4; mi++)
        #pragma unroll
        for (int ni = 0; ni < 4; ni++)
            #pragma unroll
            for (int q = 0; q < 4; q++) acc[mi][ni][q] = 0.f;

    const int a_row = tid >> 1;
    const int a_q0  = (tid & 1) * 4;
    const int b_row = tid >> 5;
    const int b_q   = (tid & 31) * 4;

    const uint32_t as_base = smem_u32(As);
    const uint32_t a_frag_off =
        (uint32_t)(((lane & 15) * 20 + (lane >> 4) * 4) * 4);

    const float* Arow = A + (size_t)(m0 + a_row) * Kfull + koff;
    const float* Bbas = Bw + (size_t)koff * FF + n0;

    float4 ar0, ar1, br0, br1;
    auto gload = [&](int k0) {
        ar0 = *(const float4*)(Arow + k0 + a_q0);
        ar1 = *(const float4*)(Arow + k0 + a_q0 + 8);
        br0 = *(const float4*)(Bbas + (size_t)(k0 + b_row) * FF + b_q);
        br1 = *(const float4*)(Bbas + (size_t)(k0 + b_row + 8) * FF + b_q);
    };
    auto sstore = [&](int buf) {
        float4 t0, t1;
        t0.x = __uint_as_float(to_tf32(ar0.x));
        t0.y = __uint_as_float(to_tf32(ar0.y));
        t0.z = __uint_as_float(to_tf32(ar0.z));
        t0.w = __uint_as_float(to_tf32(ar0.w));
        t1.x = __uint_as_float(to_tf32(ar1.x));
        t1.y = __uint_as_float(to_tf32(ar1.y));
        t1.z = __uint_as_float(to_tf32(ar1.z));
        t1.w = __uint_as_float(to_tf32(ar1.w));
        *(float4*)&As[buf][a_row][a_q0]     = t0;
        *(float4*)&As[buf][a_row][a_q0 + 8] = t1;
        float4 u0, u1;
        u0.x = __uint_as_float(to_tf32(br0.x));
        u0.y = __uint_as_float(to_tf32(br0.y));
        u0.z = __uint_as_float(to_tf32(br0.z));
        u0.w = __uint_as_float(to_tf32(br0.w));
        u1.x = __uint_as_float(to_tf32(br1.x));
        u1.y = __uint_as_float(to_tf32(br1.y));
        u1.z = __uint_as_float(to_tf32(br1.z));
        u1.w = __uint_as_float(to_tf32(br1.w));
        *(float4*)&Bs[buf][b_row][b_q]     = u0;
        *(float4*)&Bs[buf][b_row + 8][b_q] = u1;
    };

    gload(0);
    sstore(0);
    __syncthreads();

    const int KT = Keff >> 4;
    for (int kt = 0; kt < KT; kt++) {
        const int cur = kt & 1;
        if (kt + 1 < KT) gload((kt + 1) << 4);

        const uint32_t as_cur = as_base + (uint32_t)cur * sizeof(As[0]);
        #pragma unroll
        for (int kk = 0; kk < 16; kk += 8) {
            uint32_t af[4][4];
            #pragma unroll
            for (int mi = 0; mi < 4; mi++) {
                uint32_t addr = as_cur +
                    (uint32_t)((wm * 64 + mi * 16) * 80 + kk * 4) + a_frag_off;
                asm volatile(
                    "ldmatrix.sync.aligned.m8n8.x4.shared.b16 {%0,%1,%2,%3}, [%4];"
                    : "=r"(af[mi][0]), "=r"(af[mi][1]),
                      "=r"(af[mi][2]), "=r"(af[mi][3])
                    : "r"(addr));
            }
            uint32_t bf[4][2];
            #pragma unroll
            for (int ni = 0; ni < 4; ni++) {
                int c = wn * 32 + ni * 8 + g;
                bf[ni][0] = __float_as_uint(Bs[cur][kk + tq][c]);
                bf[ni][1] = __float_as_uint(Bs[cur][kk + tq + 4][c]);
            }
            #pragma unroll
            for (int mi = 0; mi < 4; mi++)
                #pragma unroll
                for (int ni = 0; ni < 4; ni++)
                    asm volatile(
                        "mma.sync.aligned.m16n8k8.row.col.f32.tf32.tf32.f32 "
                        "{%0,%1,%2,%3}, {%4,%5,%6,%7}, {%8,%9}, {%0,%1,%2,%3};"
                        : "+f"(acc[mi][ni][0]), "+f"(acc[mi][ni][1]),
                          "+f"(acc[mi][ni][2]), "+f"(acc[mi][ni][3])
                        : "r"(af[mi][0]), "r"(af[mi][1]), "r"(af[mi][2]),
                          "r"(af[mi][3]), "r"(bf[ni][0]), "r"(bf[ni][1]));
        }

        if (kt + 1 < KT) sstore(cur ^ 1);
        __syncthreads();
    }

    // epilogue: raw partial store
    float* P = part + (size_t)z * T_TOK * FF;
    #pragma unroll
    for (int mi = 0; mi < 4; mi++) {
        int r0 = m0 + wm * 64 + mi * 16 + g;
        #pragma unroll
        for (int rr = 0; rr < 2; rr++) {
            int row = r0 + rr * 8;
            #pragma unroll
            for (int ni = 0; ni < 4; ni++) {
                int col = n0 + wn * 32 + ni * 8 + tq * 2;
                float2 v;
                v.x = acc[mi][ni][rr * 2 + 0];
                v.y = acc[mi][ni][rr * 2 + 1];
                *(float2*)&P[(size_t)row * FF + col] = v;
            }
        }
    }
}

// ---------------- reduce: out = relu(p0 + p1 + bias (+ yv[tbi[row]])) -------
__global__ void __launch_bounds__(256) reduce_fuse(
    const float* __restrict__ bias, float* __restrict__ out, int add_vis) {
    int i   = blockIdx.x * 256 + threadIdx.x;   // float4 index
    int row = i >> 8;                           // 256 float4 per row
    int c4  = i & 255;
    float4 p0 = *(const float4*)&g_part[0][row][c4 * 4];
    float4 p1 = *(const float4*)&g_part[1][row][c4 * 4];
    float4 b  = *(const float4*)&bias[c4 * 4];
    float4 v;
    v.x = p0.x + p1.x + b.x;
    v.y = p0.y + p1.y + b.y;
    v.z = p0.z + p1.z + b.z;
    v.w = p0.w + p1.w + b.w;
    if (add_vis) {
        float4 y = *(const float4*)&g_yv[g_tbi[row]][c4 * 4];
        v.x += y.x; v.y += y.y; v.z += y.z; v.w += y.w;
    }
    v.x = fmaxf(v.x, 0.f);
    v.y = fmaxf(v.y, 0.f);
    v.z = fmaxf(v.z, 0.f);
    v.w = fmaxf(v.w, 0.f);
    *(float4*)&out[(size_t)row * FF + c4 * 4] = v;
}

// ---------------- head: out[2048,6] = h4 @ W5 + b5 (warp per token) ---------
__global__ void __launch_bounds__(256) head_kernel(
    const float* __restrict__ H, const float* __restrict__ W5,
    const float* __restrict__ b5, float* __restrict__ out) {
    int t    = blockIdx.x * 8 + (threadIdx.x >> 5);
    int lane = threadIdx.x & 31;
    float a0 = 0, a1 = 0, a2 = 0, a3 = 0, a4 = 0, a5 = 0;
    const float* h = H + (size_t)t * FF;
    for (int k = lane; k < FF; k += 32) {
        float hv = h[k];
        const float2 w01 = *(const float2*)&W5[(size_t)k * 6 + 0];
        const float2 w23 = *(const float2*)&W5[(size_t)k * 6 + 2];
        const float2 w45 = *(const float2*)&W5[(size_t)k * 6 + 4];
        a0 = fmaf(hv, w01.x, a0);
        a1 = fmaf(hv, w01.y, a1);
        a2 = fmaf(hv, w23.x, a2);
        a3 = fmaf(hv, w23.y, a3);
        a4 = fmaf(hv, w45.x, a4);
        a5 = fmaf(hv, w45.y, a5);
    }
    #pragma unroll
    for (int o = 16; o; o >>= 1) {
        a0 += __shfl_down_sync(~0u, a0, o);
        a1 += __shfl_down_sync(~0u, a1, o);
        a2 += __shfl_down_sync(~0u, a2, o);
        a3 += __shfl_down_sync(~0u, a3, o);
        a4 += __shfl_down_sync(~0u, a4, o);
        a5 += __shfl_down_sync(~0u, a5, o);
    }
    if (lane == 0) {
        float* o = out + (size_t)t * 6;
        o[0] = a0 + b5[0];
        o[1] = a1 + b5[1];
        o[2] = a2 + b5[2];
        o[3] = a3 + b5[3];
        o[4] = a4 + b5[4];
        o[5] = a5 + b5[5];
    }
}

// ---------------- launch -----------------------------------------------------
extern "C" void kernel_launch(void* const* d_in, const int* in_sizes, int n_in,
                              void* d_out, int out_size) {
    const float* grd     = (const float*)d_in[0];
    const float* vis     = (const float*)d_in[1];
    const int*   tbi_raw = (const int*)d_in[2];
    const float* W1 = (const float*)d_in[3];
    const float* b1 = (const float*)d_in[4];
    const float* W2 = (const float*)d_in[5];
    const float* b2 = (const float*)d_in[6];
    const float* W3 = (const float*)d_in[7];
    const float* b3 = (const float*)d_in[8];
    const float* W4 = (const float*)d_in[9];
    const float* b4 = (const float*)d_in[10];
    const float* W5 = (const float*)d_in[11];
    const float* b5 = (const float*)d_in[12];
    float* out = (float*)d_out;

    float *h0, *h1, *part;
    cudaGetSymbolAddress((void**)&h0, g_h0);
    cudaGetSymbolAddress((void**)&h1, g_h1);
    cudaGetSymbolAddress((void**)&part, g_part);

    const dim3 gg(8, 16, 2);   // split-K=2 -> 256 CTAs
    const int RB = T_TOK * FF / (256 * 4);  // reduce blocks = 2048

    resolve_idx_kernel<<<1, 1024>>>(tbi_raw);
    vis_gemm_partial<<<NVCH, 256>>>(vis, W1);
    vis_reduce<<<64, 256>>>();

    mlp_gemm<<<gg, 256>>>(grd, W1 + (size_t)VIS * FF, part, LM);
    reduce_fuse<<<RB, 256>>>(b1, h0, 1);
    mlp_gemm<<<gg, 256>>>(h0, W2, part, FF);
    reduce_fuse<<<RB, 256>>>(b2, h1, 0);
    mlp_gemm<<<gg, 256>>>(h1, W3, part, FF);
    reduce_fuse<<<RB, 256>>>(b3, h0, 0);
    mlp_gemm<<<gg, 256>>>(h0, W4, part, FF);
    reduce_fuse<<<RB, 256>>>(b4, h1, 0);
    head_kernel<<<256, 256>>>(h1, W5, b5, out);
}